// round 1
// baseline (speedup 1.0000x reference)
#include <cuda_runtime.h>

// LocalizationLoss fused single-pass reduction.
// output: (B, 3, 7) f32 ; target: (B, 3, 5) f32 [presence, x, y, wh, cls]
// loss = 0.5 + mean_{b,n}[ 5*lx^2 + 5*ly^2 + 10*lwh^2 + 3*nll - 0.5*bce_term ]

#define B_TOTAL   1048576
#define NANCH     3
#define OC        7   // output channels
#define TC        5   // target channels
#define TPB       256 // threads per block == batches per block

__device__ double g_acc;

__global__ void ll_init_kernel() { g_acc = 0.0; }

__global__ void __launch_bounds__(TPB) ll_main_kernel(const float* __restrict__ gout,
                                                      const float* __restrict__ gtgt) {
    __shared__ float sOut[TPB * NANCH * OC];   // 21504 B
    __shared__ float sTgt[TPB * NANCH * TC];   // 15360 B
    __shared__ float wsum[TPB / 32];

    const int tid = threadIdx.x;
    const long long blockBase = (long long)blockIdx.x * TPB;

    // -------- coalesced float4 staging (spans are 16B-aligned) --------
    const float4* g4o = reinterpret_cast<const float4*>(gout + blockBase * (NANCH * OC));
    const float4* g4t = reinterpret_cast<const float4*>(gtgt + blockBase * (NANCH * TC));
    float4* s4o = reinterpret_cast<float4*>(sOut);
    float4* s4t = reinterpret_cast<float4*>(sTgt);

    constexpr int N4O = TPB * NANCH * OC / 4;  // 1344
    constexpr int N4T = TPB * NANCH * TC / 4;  //  960
    #pragma unroll
    for (int i = tid; i < N4O; i += TPB) s4o[i] = g4o[i];
    #pragma unroll
    for (int i = tid; i < N4T; i += TPB) s4t[i] = g4t[i];
    __syncthreads();

    // -------- per-batch loss terms (strides 21/15 are odd -> no bank conflicts) --------
    const float* o  = sOut + tid * (NANCH * OC);
    const float* tg = sTgt + tid * (NANCH * TC);

    float acc = 0.0f;
    float l[NANCH][3];   // masked class logits, l[anchor][class]
    int   cls[NANCH];

    #pragma unroll
    for (int n = 0; n < NANCH; n++) {
        const float p = o[n * OC + 0];
        const float t = tg[n * TC + 0];

        // bce term: t*log(p) + (1-t)*log(1-p)
        const float bce = t * __logf(p) + (1.0f - t) * __logf(1.0f - p);

        const float mask = (t != 0.0f) ? 1.0f : 0.0f;

        const float lx = mask * o[n * OC + 1] - tg[n * TC + 1];
        const float ly = mask * o[n * OC + 2] - tg[n * TC + 2];

        // sq_pred = mask ? sqrt(out_wh) : 0   (out_wh in (0,1), sqrt always valid)
        const float sp  = mask * __fsqrt_rn(o[n * OC + 3]);
        const float lwh = sp - __fsqrt_rn(tg[n * TC + 3]);

        acc += 5.0f * (lx * lx + ly * ly) + 10.0f * (lwh * lwh) - 0.5f * bce;

        cls[n] = (int)tg[n * TC + 4];
        #pragma unroll
        for (int c = 0; c < 3; c++) l[n][c] = mask * o[n * OC + 4 + c];
    }

    // log_softmax over anchors (axis=1) per class column, then NLL gather
    #pragma unroll
    for (int c = 0; c < 3; c++) {
        const float m = fmaxf(l[0][c], fmaxf(l[1][c], l[2][c]));
        const float s = __expf(l[0][c] - m) + __expf(l[1][c] - m) + __expf(l[2][c] - m);
        const float lse = m + __logf(s);
        // nll_c = lse - l[cls[c]][c]   (take_along_axis over anchor dim)
        const float sel = (cls[c] == 0) ? l[0][c] : ((cls[c] == 1) ? l[1][c] : l[2][c]);
        acc += 3.0f * (lse - sel);
    }

    // -------- block reduction --------
    #pragma unroll
    for (int off = 16; off > 0; off >>= 1)
        acc += __shfl_xor_sync(0xFFFFFFFFu, acc, off);
    if ((tid & 31) == 0) wsum[tid >> 5] = acc;
    __syncthreads();
    if (tid == 0) {
        float s = 0.0f;
        #pragma unroll
        for (int w = 0; w < TPB / 32; w++) s += wsum[w];
        atomicAdd(&g_acc, (double)s);
    }
}

__global__ void ll_final_kernel(float* __restrict__ out) {
    out[0] = (float)(0.5 + g_acc / (double)((long long)B_TOTAL * NANCH));
}

extern "C" void kernel_launch(void* const* d_in, const int* in_sizes, int n_in,
                              void* d_out, int out_size) {
    // Identify inputs by element count (output: B*21, target: B*15)
    const float* gout = (const float*)d_in[0];
    const float* gtgt = (const float*)d_in[1];
    if (n_in >= 2 && in_sizes[0] == B_TOTAL * NANCH * TC) {
        gout = (const float*)d_in[1];
        gtgt = (const float*)d_in[0];
    }

    ll_init_kernel<<<1, 1>>>();
    ll_main_kernel<<<B_TOTAL / TPB, TPB>>>(gout, gtgt);
    ll_final_kernel<<<1, 1>>>((float*)d_out);
}